// round 1
// baseline (speedup 1.0000x reference)
#include <cuda_runtime.h>
#include <cuda_bf16.h>
#include <mma.h>

using namespace nvcuda;

static constexpr int N_EMBD = 1024;
static constexpr int D_FF   = 4096;
static constexpr int MAX_M  = 8192;
static constexpr int R      = 16;

// ---------------- scratch (device globals; no allocations allowed) ----------
__device__ __nv_bfloat16 g_xq[(size_t)MAX_M * N_EMBD];      // 16 MB
__device__ __nv_bfloat16 g_wq_fc[(size_t)D_FF * N_EMBD];    // 8 MB
__device__ __nv_bfloat16 g_wq_proj[(size_t)N_EMBD * D_FF];  // 8 MB
__device__ float         g_h[(size_t)MAX_M * D_FF];         // 128 MB
__device__ __nv_bfloat16 g_hq[(size_t)MAX_M * D_FF];        // 64 MB
__device__ float         g_t1[(size_t)MAX_M * R];
__device__ float         g_t2[(size_t)MAX_M * R];
__device__ int           g_maxbits[4];  // |x|, |W_fc|, |W_proj|, |h|  as float bits

// ---------------------------------------------------------------------------
__global__ void init_kernel(int* mb) {
    if (threadIdx.x < 4) mb[threadIdx.x] = 0;
}

// grid-stride abs-max over float4 data (n divisible by 4), atomicMax on bits
// (valid: values are non-negative so int compare == float compare)
__global__ void absmax_kernel(const float4* __restrict__ x, int n4, int* __restrict__ out) {
    float m = 0.f;
    for (int i = blockIdx.x * blockDim.x + threadIdx.x; i < n4; i += gridDim.x * blockDim.x) {
        float4 v = x[i];
        m = fmaxf(m, fmaxf(fmaxf(fabsf(v.x), fabsf(v.y)), fmaxf(fabsf(v.z), fabsf(v.w))));
    }
    #pragma unroll
    for (int o = 16; o; o >>= 1) m = fmaxf(m, __shfl_down_sync(0xffffffffu, m, o));
    __shared__ float sm[8];
    if ((threadIdx.x & 31) == 0) sm[threadIdx.x >> 5] = m;
    __syncthreads();
    if (threadIdx.x == 0) {
        float mm = sm[0];
        #pragma unroll
        for (int w = 1; w < 8; w++) mm = fmaxf(mm, sm[w]);
        atomicMax(out, __float_as_int(mm));
    }
}

// Per row: T[row, 0..15] = sum_k X[row,k] * A[r,k]   (A: [16,K] fp32)
// Fused: also reduces max|X| into maxout. One block (256 thr) per row.
__global__ void rowdot_max_kernel(const float* __restrict__ X, const float* __restrict__ A,
                                  int K, float* __restrict__ T, int* __restrict__ maxout) {
    __shared__ float Asm[16 * 512];
    __shared__ float red[8 * 16];
    __shared__ float mred[8];
    const int row = blockIdx.x, tid = threadIdx.x;
    const float* xrow = X + (size_t)row * K;
    float acc[16];
    #pragma unroll
    for (int r = 0; r < 16; r++) acc[r] = 0.f;
    float mx = 0.f;

    for (int c0 = 0; c0 < K; c0 += 512) {
        for (int i = tid; i < 16 * 512; i += 256) {
            int r = i >> 9, j = i & 511;
            Asm[i] = A[(size_t)r * K + c0 + j];
        }
        __syncthreads();
        for (int k = tid; k < 512; k += 256) {
            float xv = xrow[c0 + k];
            mx = fmaxf(mx, fabsf(xv));
            #pragma unroll
            for (int r = 0; r < 16; r++) acc[r] += xv * Asm[r * 512 + k];
        }
        __syncthreads();
    }
    #pragma unroll
    for (int r = 0; r < 16; r++) {
        float v = acc[r];
        #pragma unroll
        for (int o = 16; o; o >>= 1) v += __shfl_down_sync(0xffffffffu, v, o);
        if ((tid & 31) == 0) red[(tid >> 5) * 16 + r] = v;
    }
    #pragma unroll
    for (int o = 16; o; o >>= 1) mx = fmaxf(mx, __shfl_down_sync(0xffffffffu, mx, o));
    if ((tid & 31) == 0) mred[tid >> 5] = mx;
    __syncthreads();
    if (tid < 16) {
        float s = 0.f;
        #pragma unroll
        for (int w = 0; w < 8; w++) s += red[w * 16 + tid];
        T[(size_t)row * 16 + tid] = s;
    }
    if (tid == 0) {
        float m = mred[0];
        #pragma unroll
        for (int w = 1; w < 8; w++) m = fmaxf(m, mred[w]);
        atomicMax(maxout, __float_as_int(m));
    }
}

// q = clip(round(v / scale), -127, 127) stored as EXACT integer in bf16.
// scale = max(maxabs, 1e-8) / 127  — replicates reference fp32 math (IEEE div).
__global__ void quant_kernel(const float4* __restrict__ src, int n4,
                             const int* __restrict__ mb, __nv_bfloat16* __restrict__ dst) {
    const float s = fmaxf(__int_as_float(*mb), 1e-8f) / 127.0f;
    for (int i = blockIdx.x * blockDim.x + threadIdx.x; i < n4; i += gridDim.x * blockDim.x) {
        float4 v = src[i];
        float q0 = fminf(fmaxf(rintf(v.x / s), -127.f), 127.f);
        float q1 = fminf(fmaxf(rintf(v.y / s), -127.f), 127.f);
        float q2 = fminf(fmaxf(rintf(v.z / s), -127.f), 127.f);
        float q3 = fminf(fmaxf(rintf(v.w / s), -127.f), 127.f);
        __nv_bfloat162 lo, hi;
        lo.x = __float2bfloat16_rn(q0); lo.y = __float2bfloat16_rn(q1);
        hi.x = __float2bfloat16_rn(q2); hi.y = __float2bfloat16_rn(q3);
        ((__nv_bfloat162*)dst)[2 * (size_t)i]     = lo;
        ((__nv_bfloat162*)dst)[2 * (size_t)i + 1] = hi;
    }
}

// ---------------------------------------------------------------------------
// GEMM: C[m,n] = s * sum_k Aq[m,k]*Bq[n,k] + bias[n] + 2.0 * sum_j T[m,j]*Blora[n,j]
// (optionally exact-erf GELU). Aq/Bq hold exact integer values in bf16 -> the
// bf16 HMMA with fp32 accumulate reproduces the int8 GEMM exactly.
// Tiles: BM=128, BN=64, BK=32. 8 warps: 4 along M x 2 along N, warp = 32x32.
// ---------------------------------------------------------------------------
template <bool GELU>
__global__ void __launch_bounds__(256, 2) gemm_ep_kernel(
    const __nv_bfloat16* __restrict__ Aq, const __nv_bfloat16* __restrict__ Bq,
    const float* __restrict__ bias, const float* __restrict__ T,
    const float* __restrict__ Blora, const int* __restrict__ mbA,
    const int* __restrict__ mbW, float* __restrict__ C, int M, int N, int K)
{
    constexpr int BM = 128, BN = 64, BK = 32;
    constexpr int LDA = 48, LDB = 48;   // skewed strides (96B): 32B-aligned rows, no conflicts

    __shared__ alignas(16) char smem_raw[45312];
    __nv_bfloat16* As = (__nv_bfloat16*)smem_raw;               // [128][48]  = 12288 B
    __nv_bfloat16* Bs = (__nv_bfloat16*)(smem_raw + 12288);     // [64][48]   =  6144 B
    float* Csm = (float*)smem_raw;                              // [128][64]  = 32768 B (aliases As/Bs, used after)
    float* Tsm = (float*)(smem_raw + 32768);                    // [128][16]  =  8192 B
    float* Bl  = (float*)(smem_raw + 40960);                    // [64][17]   =  4352 B (17: kill bank conflicts)

    const int tid = threadIdx.x;
    const int m0 = blockIdx.y * BM, n0 = blockIdx.x * BN;
    const int w = tid >> 5, wm = w & 3, wn = w >> 2;

    // LoRA tiles for the epilogue (region doesn't alias As/Bs/Csm)
    for (int i = tid; i < BM * R / 4; i += 256)  // 512 float4, T is row-contiguous
        ((float4*)Tsm)[i] = ((const float4*)(T + (size_t)m0 * R))[i];
    for (int i = tid; i < BN * R; i += 256) {
        int r = i >> 4, j = i & 15;
        Bl[r * 17 + j] = Blora[(size_t)(n0 + r) * R + j];
    }

    wmma::fragment<wmma::accumulator, 16, 16, 16, float> cf[2][2];
    #pragma unroll
    for (int i = 0; i < 2; i++)
        #pragma unroll
        for (int j = 0; j < 2; j++) wmma::fill_fragment(cf[i][j], 0.f);

    const int ktiles = K / BK;
    for (int kt = 0; kt < ktiles; kt++) {
        const __nv_bfloat16* Ag = Aq + (size_t)m0 * K + kt * BK;
        #pragma unroll
        for (int i = tid; i < 512; i += 256) {              // 128 rows x 4 uint4
            int r = i >> 2, c = i & 3;
            *(uint4*)(As + r * LDA + c * 8) = *(const uint4*)(Ag + (size_t)r * K + c * 8);
        }
        const __nv_bfloat16* Bg = Bq + (size_t)n0 * K + kt * BK;
        {                                                   // 64 rows x 4 uint4 = 256
            int r = tid >> 2, c = tid & 3;
            *(uint4*)(Bs + r * LDB + c * 8) = *(const uint4*)(Bg + (size_t)r * K + c * 8);
        }
        __syncthreads();
        #pragma unroll
        for (int kk = 0; kk < 2; kk++) {
            wmma::fragment<wmma::matrix_a, 16, 16, 16, __nv_bfloat16, wmma::row_major> af[2];
            wmma::fragment<wmma::matrix_b, 16, 16, 16, __nv_bfloat16, wmma::col_major> bf[2];
            wmma::load_matrix_sync(af[0], As + (wm * 32)      * LDA + kk * 16, LDA);
            wmma::load_matrix_sync(af[1], As + (wm * 32 + 16) * LDA + kk * 16, LDA);
            wmma::load_matrix_sync(bf[0], Bs + (wn * 32)      * LDB + kk * 16, LDB);
            wmma::load_matrix_sync(bf[1], Bs + (wn * 32 + 16) * LDB + kk * 16, LDB);
            #pragma unroll
            for (int i = 0; i < 2; i++)
                #pragma unroll
                for (int j = 0; j < 2; j++)
                    wmma::mma_sync(cf[i][j], af[i], bf[j], cf[i][j]);
        }
        __syncthreads();
    }

    // Park accumulators in smem so the epilogue has a simple element mapping
    #pragma unroll
    for (int i = 0; i < 2; i++)
        #pragma unroll
        for (int j = 0; j < 2; j++)
            wmma::store_matrix_sync(Csm + (size_t)(wm * 32 + i * 16) * 64 + wn * 32 + j * 16,
                                    cf[i][j], 64, wmma::mem_row_major);
    __syncthreads();

    const float sA = fmaxf(__int_as_float(*mbA), 1e-8f) / 127.0f;
    const float sW = fmaxf(__int_as_float(*mbW), 1e-8f) / 127.0f;
    const float s = sA * sW;

    for (int idx = tid; idx < BM * BN; idx += 256) {
        int r = idx >> 6, c = idx & 63;
        float v = s * Csm[idx] + bias[n0 + c];
        float lor = 0.f;
        #pragma unroll
        for (int j = 0; j < 16; j++) lor += Tsm[r * 16 + j] * Bl[c * 17 + j];
        v += 2.0f * lor;                         // LORA_SCALE = 32/16 = 2
        if (GELU) v = 0.5f * v * (1.0f + erff(v * 0.7071067811865476f));
        C[(size_t)(m0 + r) * N + n0 + c] = v;
    }
}

// ---------------------------------------------------------------------------
extern "C" void kernel_launch(void* const* d_in, const int* in_sizes, int n_in,
                              void* d_out, int out_size) {
    const float* x      = (const float*)d_in[0];
    const float* W_fc   = (const float*)d_in[1];
    const float* b_fc   = (const float*)d_in[2];
    const float* A_fc   = (const float*)d_in[3];
    const float* B_fc   = (const float*)d_in[4];
    const float* W_proj = (const float*)d_in[5];
    const float* b_proj = (const float*)d_in[6];
    const float* A_proj = (const float*)d_in[7];
    const float* B_proj = (const float*)d_in[8];
    float* out = (float*)d_out;

    const int M = in_sizes[0] / N_EMBD;   // 8192

    void* p;
    cudaGetSymbolAddress(&p, g_xq);      __nv_bfloat16* xq      = (__nv_bfloat16*)p;
    cudaGetSymbolAddress(&p, g_wq_fc);   __nv_bfloat16* wq_fc   = (__nv_bfloat16*)p;
    cudaGetSymbolAddress(&p, g_wq_proj); __nv_bfloat16* wq_proj = (__nv_bfloat16*)p;
    cudaGetSymbolAddress(&p, g_h);       float* h  = (float*)p;
    cudaGetSymbolAddress(&p, g_hq);      __nv_bfloat16* hq = (__nv_bfloat16*)p;
    cudaGetSymbolAddress(&p, g_t1);      float* t1 = (float*)p;
    cudaGetSymbolAddress(&p, g_t2);      float* t2 = (float*)p;
    cudaGetSymbolAddress(&p, g_maxbits); int* mb   = (int*)p;

    init_kernel<<<1, 32>>>(mb);

    // weight abs-max (independent of activations)
    absmax_kernel<<<512, 256>>>((const float4*)W_fc,   D_FF * N_EMBD / 4, mb + 1);
    absmax_kernel<<<512, 256>>>((const float4*)W_proj, N_EMBD * D_FF / 4, mb + 2);

    // fused max|x| + t1 = x @ A_fc^T
    rowdot_max_kernel<<<M, 256>>>(x, A_fc, N_EMBD, t1, mb + 0);

    // quantize to exact-integer bf16
    quant_kernel<<<2048, 256>>>((const float4*)x,      M * N_EMBD / 4,    mb + 0, xq);
    quant_kernel<<<1024, 256>>>((const float4*)W_fc,   D_FF * N_EMBD / 4, mb + 1, wq_fc);
    quant_kernel<<<1024, 256>>>((const float4*)W_proj, N_EMBD * D_FF / 4, mb + 2, wq_proj);

    // GEMM1 + bias + LoRA + GELU -> h (fp32)
    gemm_ep_kernel<true><<<dim3(D_FF / 64, M / 128), 256>>>(
        xq, wq_fc, b_fc, t1, B_fc, mb + 0, mb + 1, h, M, D_FF, N_EMBD);

    // fused max|h| + t2 = h @ A_proj^T
    rowdot_max_kernel<<<M, 256>>>(h, A_proj, D_FF, t2, mb + 3);

    // quantize h
    quant_kernel<<<4096, 256>>>((const float4*)h, M * D_FF / 4, mb + 3, hq);

    // GEMM2 + bias + LoRA -> out
    gemm_ep_kernel<false><<<dim3(N_EMBD / 64, M / 128), 256>>>(
        hq, wq_proj, b_proj, t2, B_proj, mb + 3, mb + 2, out, M, N_EMBD, D_FF);
}

// round 2
// speedup vs baseline: 1.5339x; 1.5339x over previous
#include <cuda_runtime.h>
#include <cuda_bf16.h>
#include <mma.h>

using namespace nvcuda;

static constexpr int N_EMBD = 1024;
static constexpr int D_FF   = 4096;
static constexpr int MAX_M  = 8192;
static constexpr int R      = 16;
static constexpr int NB2    = D_FF / 64;   // # n-blocks in GEMM1 = t2 partial slices

// ---------------- scratch (device globals; no allocations allowed) ----------
__device__ __nv_bfloat16 g_xq[(size_t)MAX_M * N_EMBD];
__device__ __nv_bfloat16 g_wq_fc[(size_t)D_FF * N_EMBD];
__device__ __nv_bfloat16 g_wq_proj[(size_t)N_EMBD * D_FF];
__device__ float         g_h[(size_t)MAX_M * D_FF];          // 128 MB
__device__ __nv_bfloat16 g_hq[(size_t)MAX_M * D_FF];         // 64 MB
__device__ float         g_t1[(size_t)MAX_M * R];
__device__ float         g_t2[(size_t)MAX_M * R];
__device__ float         g_tpart[(size_t)NB2 * MAX_M * R];   // 32 MB
__device__ int           g_maxbits[4];                       // |x|,|W_fc|,|W_proj|,|h|

__device__ __forceinline__ void cp_async16(void* d, const void* s) {
    unsigned u = (unsigned)__cvta_generic_to_shared(d);
    asm volatile("cp.async.cg.shared.global [%0], [%1], 16;\n" :: "r"(u), "l"(s));
}

// ---------------------------------------------------------------------------
__global__ void init_kernel(int* mb) { if (threadIdx.x < 4) mb[threadIdx.x] = 0; }

__global__ void absmax_kernel(const float4* __restrict__ x, int n4, int* __restrict__ out) {
    float m = 0.f;
    for (int i = blockIdx.x * blockDim.x + threadIdx.x; i < n4; i += gridDim.x * blockDim.x) {
        float4 v = x[i];
        m = fmaxf(m, fmaxf(fmaxf(fabsf(v.x), fabsf(v.y)), fmaxf(fabsf(v.z), fabsf(v.w))));
    }
    #pragma unroll
    for (int o = 16; o; o >>= 1) m = fmaxf(m, __shfl_down_sync(0xffffffffu, m, o));
    __shared__ float sm[8];
    if ((threadIdx.x & 31) == 0) sm[threadIdx.x >> 5] = m;
    __syncthreads();
    if (threadIdx.x == 0) {
        float mm = sm[0];
        #pragma unroll
        for (int w = 1; w < 8; w++) mm = fmaxf(mm, sm[w]);
        atomicMax(out, __float_as_int(mm));
    }
}

// ---------------------------------------------------------------------------
// t1 = X @ A^T  (A: [16,K]) as a register-tiled tall-skinny GEMM, fused abs-max.
// BM=128 rows/block, 128 threads, thread tile 4 rows x 4 cols, BK=32, reg prefetch.
// ---------------------------------------------------------------------------
__global__ void __launch_bounds__(128) rowdot_x_kernel(
    const float* __restrict__ X, const float* __restrict__ A, int K,
    float* __restrict__ T, int* __restrict__ maxout)
{
    constexpr int LDS = 40;  // 160B rows: 16B aligned, 8-bank skew
    __shared__ __align__(16) float Xs[128 * LDS];
    __shared__ __align__(16) float As[16 * LDS];
    __shared__ float mred[4];
    const int tid = threadIdx.x;
    const int m0  = blockIdx.x * 128;
    const int rg  = tid >> 2, cg = tid & 3;
    const float* Xg = X + (size_t)m0 * K;

    float acc[4][4] = {};
    float mx = 0.f;
    float4 xreg[8], areg;

    auto preload = [&](int kt) {
        #pragma unroll
        for (int l = 0; l < 8; l++) {
            int i = tid + l * 128, row = i >> 3, c = (i & 7) * 4;
            xreg[l] = *(const float4*)(Xg + (size_t)row * K + kt * 32 + c);
        }
        { int row = tid >> 3, c = (tid & 7) * 4;
          areg = *(const float4*)(A + (size_t)row * K + kt * 32 + c); }
    };

    const int KT = K / 32;
    preload(0);
    for (int kt = 0; kt < KT; kt++) {
        #pragma unroll
        for (int l = 0; l < 8; l++) {
            int i = tid + l * 128, row = i >> 3, c = (i & 7) * 4;
            *(float4*)(Xs + row * LDS + c) = xreg[l];
            float4 v = xreg[l];
            mx = fmaxf(mx, fmaxf(fmaxf(fabsf(v.x), fabsf(v.y)), fmaxf(fabsf(v.z), fabsf(v.w))));
        }
        { int row = tid >> 3, c = (tid & 7) * 4;
          *(float4*)(As + row * LDS + c) = areg; }
        __syncthreads();
        if (kt + 1 < KT) preload(kt + 1);
        #pragma unroll
        for (int kq = 0; kq < 8; kq++) {
            float4 av[4], xv[4];
            #pragma unroll
            for (int jj = 0; jj < 4; jj++) av[jj] = *(float4*)(As + (cg * 4 + jj) * LDS + kq * 4);
            #pragma unroll
            for (int ii = 0; ii < 4; ii++) xv[ii] = *(float4*)(Xs + (rg * 4 + ii) * LDS + kq * 4);
            #pragma unroll
            for (int ii = 0; ii < 4; ii++)
                #pragma unroll
                for (int jj = 0; jj < 4; jj++)
                    acc[ii][jj] += xv[ii].x * av[jj].x + xv[ii].y * av[jj].y
                                 + xv[ii].z * av[jj].z + xv[ii].w * av[jj].w;
        }
        __syncthreads();
    }
    #pragma unroll
    for (int ii = 0; ii < 4; ii++)
        #pragma unroll
        for (int jj = 0; jj < 4; jj++)
            T[(size_t)(m0 + rg * 4 + ii) * R + cg * 4 + jj] = acc[ii][jj];

    #pragma unroll
    for (int o = 16; o; o >>= 1) mx = fmaxf(mx, __shfl_down_sync(0xffffffffu, mx, o));
    if ((tid & 31) == 0) mred[tid >> 5] = mx;
    __syncthreads();
    if (tid == 0) {
        float m = fmaxf(fmaxf(mred[0], mred[1]), fmaxf(mred[2], mred[3]));
        atomicMax(maxout, __float_as_int(m));
    }
}

// q = clip(round(v/scale),-127,127) stored as EXACT integer in bf16.
__global__ void quant_kernel(const float4* __restrict__ src, int n4,
                             const int* __restrict__ mb, __nv_bfloat16* __restrict__ dst) {
    const float s = fmaxf(__int_as_float(*mb), 1e-8f) / 127.0f;
    for (int i = blockIdx.x * blockDim.x + threadIdx.x; i < n4; i += gridDim.x * blockDim.x) {
        float4 v = src[i];
        float q0 = fminf(fmaxf(rintf(v.x / s), -127.f), 127.f);
        float q1 = fminf(fmaxf(rintf(v.y / s), -127.f), 127.f);
        float q2 = fminf(fmaxf(rintf(v.z / s), -127.f), 127.f);
        float q3 = fminf(fmaxf(rintf(v.w / s), -127.f), 127.f);
        __nv_bfloat162 lo, hi;
        lo.x = __float2bfloat16_rn(q0); lo.y = __float2bfloat16_rn(q1);
        hi.x = __float2bfloat16_rn(q2); hi.y = __float2bfloat16_rn(q3);
        ((__nv_bfloat162*)dst)[2 * (size_t)i]     = lo;
        ((__nv_bfloat162*)dst)[2 * (size_t)i + 1] = hi;
    }
}

// deterministic fixed-order reduction of t2 partials
__global__ void reduce_t2_kernel(const float* __restrict__ Tpart, float* __restrict__ T2,
                                 int n, int nb) {
    int i = blockIdx.x * blockDim.x + threadIdx.x;
    if (i < n) {
        float s = 0.f;
        for (int b = 0; b < nb; b++) s += Tpart[(size_t)b * n + i];
        T2[i] = s;
    }
}

// ---------------------------------------------------------------------------
// GEMM: C = s*(Aq@Bq^T) + bias + 2*(T@Blora^T)  [+GELU]
// cp.async double-buffered, BM=128 BN=64 BK=32, 8 warps (4x2), warp 32x32.
// FUSE_T2: also emits per-block partials of gelu(h)@A_proj^T and max|h|.
// ---------------------------------------------------------------------------
template <bool GELU, bool FUSE_T2>
__global__ void __launch_bounds__(256, 2) gemm_kernel(
    const __nv_bfloat16* __restrict__ Aq, const __nv_bfloat16* __restrict__ Bq,
    const float* __restrict__ bias, const float* __restrict__ T,
    const float* __restrict__ Blora, const int* __restrict__ mbA,
    const int* __restrict__ mbW, float* __restrict__ C,
    const float* __restrict__ Ap, float* __restrict__ Tpart, int* __restrict__ hmax,
    int M, int N, int K)
{
    constexpr int BM = 128, BN = 64, BK = 32, LD = 48;
    __shared__ __align__(16) char smem[36864];   // 2 stages x (12288 A + 6144 B)
    __shared__ float hred[8];
    const int tid = threadIdx.x;
    const int m0 = blockIdx.y * BM, n0 = blockIdx.x * BN;
    const int w = tid >> 5, wm = w & 3, wn = w >> 2;

    const __nv_bfloat16* Agb = Aq + (size_t)m0 * K;
    const __nv_bfloat16* Bgb = Bq + (size_t)n0 * K;

    auto issue = [&](int kt) {
        int s = kt & 1;
        __nv_bfloat16* as = (__nv_bfloat16*)(smem + s * 18432);
        __nv_bfloat16* bs = (__nv_bfloat16*)(smem + s * 18432 + 12288);
        const __nv_bfloat16* ag = Agb + kt * BK;
        const __nv_bfloat16* bg = Bgb + kt * BK;
        #pragma unroll
        for (int l = 0; l < 2; l++) {
            int id = tid + l * 256, r = id >> 2, c = id & 3;
            cp_async16(as + r * LD + c * 8, ag + (size_t)r * K + c * 8);
        }
        { int r = tid >> 2, c = tid & 3;
          cp_async16(bs + r * LD + c * 8, bg + (size_t)r * K + c * 8); }
    };

    const int KT = K / BK;
    issue(0); asm volatile("cp.async.commit_group;\n" ::: "memory");
    issue(1); asm volatile("cp.async.commit_group;\n" ::: "memory");

    wmma::fragment<wmma::accumulator, 16, 16, 16, float> cf[2][2];
    #pragma unroll
    for (int i = 0; i < 2; i++)
        #pragma unroll
        for (int j = 0; j < 2; j++) wmma::fill_fragment(cf[i][j], 0.f);

    for (int kt = 0; kt < KT; kt++) {
        asm volatile("cp.async.wait_group 1;\n" ::: "memory");
        __syncthreads();
        int s = kt & 1;
        const __nv_bfloat16* as = (const __nv_bfloat16*)(smem + s * 18432);
        const __nv_bfloat16* bs = (const __nv_bfloat16*)(smem + s * 18432 + 12288);
        #pragma unroll
        for (int kk = 0; kk < 2; kk++) {
            wmma::fragment<wmma::matrix_a, 16, 16, 16, __nv_bfloat16, wmma::row_major> af[2];
            wmma::fragment<wmma::matrix_b, 16, 16, 16, __nv_bfloat16, wmma::col_major> bf[2];
            wmma::load_matrix_sync(af[0], as + (wm * 32)      * LD + kk * 16, LD);
            wmma::load_matrix_sync(af[1], as + (wm * 32 + 16) * LD + kk * 16, LD);
            wmma::load_matrix_sync(bf[0], bs + (wn * 32)      * LD + kk * 16, LD);
            wmma::load_matrix_sync(bf[1], bs + (wn * 32 + 16) * LD + kk * 16, LD);
            #pragma unroll
            for (int i = 0; i < 2; i++)
                #pragma unroll
                for (int j = 0; j < 2; j++)
                    wmma::mma_sync(cf[i][j], af[i], bf[j], cf[i][j]);
        }
        __syncthreads();
        if (kt + 2 < KT) issue(kt + 2);
        asm volatile("cp.async.commit_group;\n" ::: "memory");
    }
    asm volatile("cp.async.wait_group 0;\n" ::: "memory");
    __syncthreads();

    // ---------------- epilogue (aliases pipeline smem) ----------------
    const float sA = fmaxf(__int_as_float(*mbA), 1e-8f) / 127.0f;
    const float sW = fmaxf(__int_as_float(*mbW), 1e-8f) / 127.0f;
    const float sc = sA * sW;

    float* park = (float*)smem;              // 64x64        = 16384 B
    float* Tsm  = (float*)(smem + 16384);    // 64x16        =  4096 B
    float* Bl   = (float*)(smem + 20480);    // 64x17        =  4352 B
    float* Apsm = (float*)(smem + 24832);    // 16x68        =  4352 B -> 29184

    for (int i = tid; i < BN * R; i += 256) {
        int r = i >> 4, j = i & 15;
        Bl[r * 17 + j] = Blora[(size_t)(n0 + r) * R + j];
    }
    if (FUSE_T2)
        for (int i = tid; i < R * BN; i += 256) {
            int j = i >> 6, c = i & 63;
            Apsm[j * 68 + c] = Ap[(size_t)j * N + n0 + c];
        }

    float hm = 0.f;
    #pragma unroll
    for (int half = 0; half < 2; half++) {
        __syncthreads();
        if ((wm >> 1) == half) {
            #pragma unroll
            for (int i = 0; i < 2; i++)
                #pragma unroll
                for (int j = 0; j < 2; j++)
                    wmma::store_matrix_sync(
                        park + (size_t)((wm & 1) * 32 + i * 16) * 64 + wn * 32 + j * 16,
                        cf[i][j], 64, wmma::mem_row_major);
        }
        ((float4*)Tsm)[tid] = ((const float4*)(T + (size_t)(m0 + half * 64) * R))[tid];
        __syncthreads();

        for (int idx = tid; idx < 64 * 64; idx += 256) {
            int r = idx >> 6, c = idx & 63;
            float v = sc * park[idx] + __ldg(bias + n0 + c);
            float lor = 0.f;
            #pragma unroll
            for (int j = 0; j < 16; j++) lor += Tsm[r * 16 + j] * Bl[c * 17 + j];
            v += 2.0f * lor;
            if (GELU) v = 0.5f * v * (1.0f + erff(v * 0.7071067811865476f));
            C[(size_t)(m0 + half * 64 + r) * N + n0 + c] = v;
            if (FUSE_T2) { park[idx] = v; hm = fmaxf(hm, fabsf(v)); }
        }
        if (FUSE_T2) {
            __syncthreads();
            int j = tid & 15, rg = tid >> 4;
            float acc[4] = {0.f, 0.f, 0.f, 0.f};
            #pragma unroll
            for (int cq = 0; cq < 16; cq++) {
                float4 av = *(float4*)(Apsm + j * 68 + cq * 4);
                #pragma unroll
                for (int ii = 0; ii < 4; ii++) {
                    float4 hv = *(float4*)(park + (rg * 4 + ii) * 64 + cq * 4);
                    acc[ii] += hv.x * av.x + hv.y * av.y + hv.z * av.z + hv.w * av.w;
                }
            }
            #pragma unroll
            for (int ii = 0; ii < 4; ii++)
                Tpart[(size_t)blockIdx.x * ((size_t)M * R)
                      + (size_t)(m0 + half * 64 + rg * 4 + ii) * R + j] = acc[ii];
        }
    }
    if (FUSE_T2) {
        #pragma unroll
        for (int o = 16; o; o >>= 1) hm = fmaxf(hm, __shfl_down_sync(0xffffffffu, hm, o));
        if ((tid & 31) == 0) hred[w] = hm;
        __syncthreads();
        if (tid == 0) {
            float m = hred[0];
            #pragma unroll
            for (int i = 1; i < 8; i++) m = fmaxf(m, hred[i]);
            atomicMax(hmax, __float_as_int(m));
        }
    }
}

// ---------------------------------------------------------------------------
extern "C" void kernel_launch(void* const* d_in, const int* in_sizes, int n_in,
                              void* d_out, int out_size) {
    const float* x      = (const float*)d_in[0];
    const float* W_fc   = (const float*)d_in[1];
    const float* b_fc   = (const float*)d_in[2];
    const float* A_fc   = (const float*)d_in[3];
    const float* B_fc   = (const float*)d_in[4];
    const float* W_proj = (const float*)d_in[5];
    const float* b_proj = (const float*)d_in[6];
    const float* A_proj = (const float*)d_in[7];
    const float* B_proj = (const float*)d_in[8];
    float* out = (float*)d_out;

    const int M = in_sizes[0] / N_EMBD;   // 8192

    void* p;
    cudaGetSymbolAddress(&p, g_xq);      __nv_bfloat16* xq      = (__nv_bfloat16*)p;
    cudaGetSymbolAddress(&p, g_wq_fc);   __nv_bfloat16* wq_fc   = (__nv_bfloat16*)p;
    cudaGetSymbolAddress(&p, g_wq_proj); __nv_bfloat16* wq_proj = (__nv_bfloat16*)p;
    cudaGetSymbolAddress(&p, g_h);       float* h     = (float*)p;
    cudaGetSymbolAddress(&p, g_hq);      __nv_bfloat16* hq = (__nv_bfloat16*)p;
    cudaGetSymbolAddress(&p, g_t1);      float* t1    = (float*)p;
    cudaGetSymbolAddress(&p, g_t2);      float* t2    = (float*)p;
    cudaGetSymbolAddress(&p, g_tpart);   float* tpart = (float*)p;
    cudaGetSymbolAddress(&p, g_maxbits); int* mb      = (int*)p;

    init_kernel<<<1, 32>>>(mb);

    absmax_kernel<<<512, 256>>>((const float4*)W_fc,   D_FF * N_EMBD / 4, mb + 1);
    absmax_kernel<<<512, 256>>>((const float4*)W_proj, N_EMBD * D_FF / 4, mb + 2);

    // fused max|x| + t1 = x @ A_fc^T
    rowdot_x_kernel<<<M / 128, 128>>>(x, A_fc, N_EMBD, t1, mb + 0);

    quant_kernel<<<2048, 256>>>((const float4*)x,      M * N_EMBD / 4,    mb + 0, xq);
    quant_kernel<<<1024, 256>>>((const float4*)W_fc,   D_FF * N_EMBD / 4, mb + 1, wq_fc);
    quant_kernel<<<1024, 256>>>((const float4*)W_proj, N_EMBD * D_FF / 4, mb + 2, wq_proj);

    // GEMM1 + bias + LoRA + GELU -> h; fused partial t2 + max|h|
    gemm_kernel<true, true><<<dim3(D_FF / 64, M / 128), 256>>>(
        xq, wq_fc, b_fc, t1, B_fc, mb + 0, mb + 1, h,
        A_proj, tpart, mb + 3, M, D_FF, N_EMBD);

    reduce_t2_kernel<<<(M * R + 255) / 256, 256>>>(tpart, t2, M * R, NB2);

    quant_kernel<<<4096, 256>>>((const float4*)h, M * D_FF / 4, mb + 3, hq);

    // GEMM2 + bias + LoRA -> out
    gemm_kernel<false, false><<<dim3(N_EMBD / 64, M / 128), 256>>>(
        hq, wq_proj, b_proj, t2, B_proj, mb + 3, mb + 2, out,
        nullptr, nullptr, nullptr, M, N_EMBD, D_FF);
}

// round 4
// speedup vs baseline: 2.6855x; 1.7507x over previous
#include <cuda_runtime.h>
#include <cuda_bf16.h>
#include <mma.h>

using namespace nvcuda;

static constexpr int N_EMBD = 1024;
static constexpr int D_FF   = 4096;
static constexpr int MAX_M  = 8192;
static constexpr int R      = 16;
static constexpr int NB2    = D_FF / 128;   // GEMM1 n-blocks = t2 partial slices (32)

// ---------------- scratch (device globals; no allocations allowed) ----------
__device__ signed char g_xq[(size_t)MAX_M * N_EMBD];        // 8 MB
__device__ signed char g_wq_fc[(size_t)D_FF * N_EMBD];      // 4 MB
__device__ signed char g_wq_proj[(size_t)N_EMBD * D_FF];    // 4 MB
__device__ float       g_h[(size_t)MAX_M * D_FF];           // 128 MB
__device__ signed char g_hq[(size_t)MAX_M * D_FF];          // 32 MB
__device__ float       g_t1[(size_t)MAX_M * R];
__device__ float       g_t2[(size_t)MAX_M * R];
__device__ float       g_tpart[(size_t)NB2 * MAX_M * R];    // 16 MB
__device__ int         g_maxbits[4];                        // |x|,|W_fc|,|W_proj|,|h|

__device__ __forceinline__ void cp_async16(void* d, const void* s) {
    unsigned u = (unsigned)__cvta_generic_to_shared(d);
    asm volatile("cp.async.cg.shared.global [%0], [%1], 16;\n" :: "r"(u), "l"(s));
}
__device__ __forceinline__ void cp_commit() {
    asm volatile("cp.async.commit_group;\n" ::: "memory");
}

// ---------------------------------------------------------------------------
__global__ void init_kernel(int* mb) { if (threadIdx.x < 4) mb[threadIdx.x] = 0; }

__global__ void absmax_kernel(const float4* __restrict__ x, int n4, int* __restrict__ out) {
    float m = 0.f;
    for (int i = blockIdx.x * blockDim.x + threadIdx.x; i < n4; i += gridDim.x * blockDim.x) {
        float4 v = x[i];
        m = fmaxf(m, fmaxf(fmaxf(fabsf(v.x), fabsf(v.y)), fmaxf(fabsf(v.z), fabsf(v.w))));
    }
    #pragma unroll
    for (int o = 16; o; o >>= 1) m = fmaxf(m, __shfl_down_sync(0xffffffffu, m, o));
    __shared__ float sm[8];
    if ((threadIdx.x & 31) == 0) sm[threadIdx.x >> 5] = m;
    __syncthreads();
    if (threadIdx.x == 0) {
        float mm = sm[0];
        #pragma unroll
        for (int w = 1; w < 8; w++) mm = fmaxf(mm, sm[w]);
        atomicMax(out, __float_as_int(mm));
    }
}

// ---------------------------------------------------------------------------
// t1 = X @ A^T  (A:[16,K]) fused abs-max. BM=64 rows, 256 threads, 2x2 thread
// tiles, 3-stage cp.async. Low reg count -> high occupancy.
// ---------------------------------------------------------------------------
__global__ void __launch_bounds__(256) rowdot_x_kernel(
    const float* __restrict__ X, const float* __restrict__ A, int K,
    float* __restrict__ T, int* __restrict__ maxout)
{
    constexpr int LDS = 36;                       // 144B rows (16B-aligned, skewed)
    constexpr int STG = (64 + 16) * LDS;          // floats per stage = 2880
    __shared__ __align__(16) float sm[3 * STG];
    __shared__ float mred[8];
    const int tid = threadIdx.x;
    const int m0  = blockIdx.x * 64;
    const int rg  = tid >> 3, cg = tid & 7;       // 32 row-groups x 8 col-groups
    const float* Xg = X + (size_t)m0 * K;

    auto issue = [&](int kt) {
        float* Xs = sm + (kt % 3) * STG;
        float* As = Xs + 64 * LDS;
        #pragma unroll
        for (int l = 0; l < 2; l++) {
            int i = tid + l * 256, r = i >> 3, c = i & 7;
            cp_async16(Xs + r * LDS + c * 4, Xg + (size_t)r * K + kt * 32 + c * 4);
        }
        if (tid < 128) {
            int r = tid >> 3, c = tid & 7;
            cp_async16(As + r * LDS + c * 4, A + (size_t)r * K + kt * 32 + c * 4);
        }
        cp_commit();
    };

    const int KT = K / 32;
    issue(0); issue(1);
    float acc[2][2] = {};
    float mx = 0.f;

    for (int kt = 0; kt < KT; kt++) {
        asm volatile("cp.async.wait_group 1;\n" ::: "memory");
        __syncthreads();
        if (kt + 2 < KT) issue(kt + 2); else cp_commit();
        const float* Xs = sm + (kt % 3) * STG;
        const float* As = Xs + 64 * LDS;
        #pragma unroll
        for (int kq = 0; kq < 8; kq++) {
            float4 xv0 = *(const float4*)(Xs + (rg * 2)     * LDS + kq * 4);
            float4 xv1 = *(const float4*)(Xs + (rg * 2 + 1) * LDS + kq * 4);
            float4 av0 = *(const float4*)(As + (cg * 2)     * LDS + kq * 4);
            float4 av1 = *(const float4*)(As + (cg * 2 + 1) * LDS + kq * 4);
            mx = fmaxf(mx, fmaxf(fmaxf(fabsf(xv0.x), fabsf(xv0.y)), fmaxf(fabsf(xv0.z), fabsf(xv0.w))));
            mx = fmaxf(mx, fmaxf(fmaxf(fabsf(xv1.x), fabsf(xv1.y)), fmaxf(fabsf(xv1.z), fabsf(xv1.w))));
            acc[0][0] += xv0.x*av0.x + xv0.y*av0.y + xv0.z*av0.z + xv0.w*av0.w;
            acc[0][1] += xv0.x*av1.x + xv0.y*av1.y + xv0.z*av1.z + xv0.w*av1.w;
            acc[1][0] += xv1.x*av0.x + xv1.y*av0.y + xv1.z*av0.z + xv1.w*av0.w;
            acc[1][1] += xv1.x*av1.x + xv1.y*av1.y + xv1.z*av1.z + xv1.w*av1.w;
        }
        __syncthreads();
    }
    #pragma unroll
    for (int ii = 0; ii < 2; ii++)
        #pragma unroll
        for (int jj = 0; jj < 2; jj++)
            T[(size_t)(m0 + rg * 2 + ii) * R + cg * 2 + jj] = acc[ii][jj];

    #pragma unroll
    for (int o = 16; o; o >>= 1) mx = fmaxf(mx, __shfl_down_sync(0xffffffffu, mx, o));
    if ((tid & 31) == 0) mred[tid >> 5] = mx;
    __syncthreads();
    if (tid == 0) {
        float m = mred[0];
        #pragma unroll
        for (int i = 1; i < 8; i++) m = fmaxf(m, mred[i]);
        atomicMax(maxout, __float_as_int(m));
    }
}

// q = clip(round(v/scale),-127,127) stored as int8.
__global__ void quant_kernel(const float4* __restrict__ src, int n4,
                             const int* __restrict__ mb, char4* __restrict__ dst) {
    const float s = fmaxf(__int_as_float(*mb), 1e-8f) / 127.0f;
    for (int i = blockIdx.x * blockDim.x + threadIdx.x; i < n4; i += gridDim.x * blockDim.x) {
        float4 v = src[i];
        char4 q;
        q.x = (signed char)(int)fminf(fmaxf(rintf(v.x / s), -127.f), 127.f);
        q.y = (signed char)(int)fminf(fmaxf(rintf(v.y / s), -127.f), 127.f);
        q.z = (signed char)(int)fminf(fmaxf(rintf(v.z / s), -127.f), 127.f);
        q.w = (signed char)(int)fminf(fmaxf(rintf(v.w / s), -127.f), 127.f);
        dst[i] = q;
    }
}

// deterministic fixed-order reduction of t2 partials
__global__ void reduce_t2_kernel(const float* __restrict__ Tpart, float* __restrict__ T2,
                                 int n, int nb) {
    int i = blockIdx.x * blockDim.x + threadIdx.x;
    if (i < n) {
        float s = 0.f;
        for (int b = 0; b < nb; b++) s += Tpart[(size_t)b * n + i];
        T2[i] = s;
    }
}

// ---------------------------------------------------------------------------
// int8 GEMM: C = s*(Aq@Bq^T) + bias + 2*(T@Blora^T)  [+GELU]
// BM=128 BN=128 BK=64, 3-stage cp.async, wmma s8 (s32 accum, exact).
// 8 warps: 2(m) x 4(n), warp tile 64x32.
// FUSE_T2: emits per-n-block partials of gelu(h)@Ap^T and max|h|.
// ---------------------------------------------------------------------------
template <bool GELU, bool FUSE_T2>
__global__ void __launch_bounds__(256, 2) gemm_kernel(
    const signed char* __restrict__ Aq, const signed char* __restrict__ Bq,
    const float* __restrict__ bias, const float* __restrict__ T,
    const float* __restrict__ Blora, const int* __restrict__ mbA,
    const int* __restrict__ mbW, float* __restrict__ C,
    const float* __restrict__ Ap, float* __restrict__ Tpart, int* __restrict__ hmax,
    int M, int N, int K)
{
    constexpr int BM = 128, BN = 128, BK = 64, LDA = 80;
    constexpr int STAGE = 2 * BM * LDA;           // A(10240) + B(10240) bytes
    extern __shared__ __align__(16) char smem[];  // 3*20480 = 61440
    __shared__ float hred[8];

    const int tid = threadIdx.x;
    const int m0 = blockIdx.y * BM, n0 = blockIdx.x * BN;
    const int w = tid >> 5, wm = w & 1, wn = w >> 1;

    const signed char* Agb = Aq + (size_t)m0 * K;
    const signed char* Bgb = Bq + (size_t)n0 * K;

    auto issue = [&](int kt) {
        char* as = smem + (kt % 3) * STAGE;
        char* bs = as + BM * LDA;
        const signed char* ag = Agb + kt * BK;
        const signed char* bg = Bgb + kt * BK;
        #pragma unroll
        for (int l = 0; l < 2; l++) {
            int i = tid + l * 256, r = i >> 2, c = i & 3;
            cp_async16(as + r * LDA + c * 16, ag + (size_t)r * K + c * 16);
        }
        #pragma unroll
        for (int l = 0; l < 2; l++) {
            int i = tid + l * 256, r = i >> 2, c = i & 3;
            cp_async16(bs + r * LDA + c * 16, bg + (size_t)r * K + c * 16);
        }
        cp_commit();
    };

    const int KT = K / BK;
    issue(0); issue(1);

    wmma::fragment<wmma::accumulator, 16, 16, 16, int> cf[4][2];
    #pragma unroll
    for (int i = 0; i < 4; i++)
        #pragma unroll
        for (int j = 0; j < 2; j++) wmma::fill_fragment(cf[i][j], 0);

    for (int kt = 0; kt < KT; kt++) {
        asm volatile("cp.async.wait_group 1;\n" ::: "memory");
        __syncthreads();
        if (kt + 2 < KT) issue(kt + 2); else cp_commit();
        const signed char* as = (const signed char*)(smem + (kt % 3) * STAGE);
        const signed char* bs = as + BM * LDA;
        #pragma unroll
        for (int kk = 0; kk < 4; kk++) {
            wmma::fragment<wmma::matrix_a, 16, 16, 16, signed char, wmma::row_major> af[4];
            wmma::fragment<wmma::matrix_b, 16, 16, 16, signed char, wmma::col_major> bf[2];
            #pragma unroll
            for (int i = 0; i < 4; i++)
                wmma::load_matrix_sync(af[i], as + (wm * 64 + i * 16) * LDA + kk * 16, LDA);
            #pragma unroll
            for (int j = 0; j < 2; j++)
                wmma::load_matrix_sync(bf[j], bs + (wn * 32 + j * 16) * LDA + kk * 16, LDA);
            #pragma unroll
            for (int i = 0; i < 4; i++)
                #pragma unroll
                for (int j = 0; j < 2; j++)
                    wmma::mma_sync(cf[i][j], af[i], bf[j], cf[i][j]);
        }
        __syncthreads();
    }
    asm volatile("cp.async.wait_group 0;\n" ::: "memory");
    __syncthreads();

    // ---------------- epilogue (aliases pipeline smem) ----------------
    const float sA = fmaxf(__int_as_float(*mbA), 1e-8f) / 127.0f;
    const float sW = fmaxf(__int_as_float(*mbW), 1e-8f) / 127.0f;
    const float sc = sA * sW;

    int*   parkI = (int*)smem;                    // [128][68] int/float = 34816 B
    float* parkF = (float*)smem;
    float* Tsm   = (float*)(smem + 34816);        // [128][16]           =  8192 B
    float* Bl    = (float*)(smem + 43008);        // [128][17]           =  8704 B
    float* Apsm  = (float*)(smem + 51712);        // [16][132]           =  8448 B  -> 60160

    for (int i = tid; i < BN * R; i += 256) {     // Blora tile
        int r = i >> 4, j = i & 15;
        Bl[r * 17 + j] = Blora[(size_t)(n0 + r) * R + j];
    }
    if (FUSE_T2)
        for (int i = tid; i < R * BN; i += 256) { // A_proj tile [16][128]
            int j = i >> 7, c = i & 127;
            Apsm[j * 132 + c] = Ap[(size_t)j * N + n0 + c];
        }
    #pragma unroll
    for (int l = 0; l < 2; l++)                   // T tile [128][16]
        ((float4*)Tsm)[tid + l * 256] = ((const float4*)(T + (size_t)m0 * R))[tid + l * 256];

    float hm = 0.f;
    float acc2[8] = {};                           // t2 partial rows (FUSE_T2)
    const int jj = tid & 15, rgp = tid >> 4;      // t2 mapping: 16 j x 16 rowgroups(8 rows)

    #pragma unroll
    for (int half = 0; half < 2; half++) {
        __syncthreads();
        if ((wn >> 1) == half) {                  // 4 warps park their 64x64 quadrant
            #pragma unroll
            for (int i = 0; i < 4; i++)
                #pragma unroll
                for (int j = 0; j < 2; j++)
                    wmma::store_matrix_sync(parkI + (wm * 64 + i * 16) * 68 + (wn & 1) * 32 + j * 16,
                                            cf[i][j], 68, wmma::mem_row_major);
        }
        __syncthreads();

        for (int idx = tid; idx < BM * 64; idx += 256) {
            int r = idx >> 6, c = idx & 63;
            int gc = half * 64 + c;
            float v = sc * (float)parkI[r * 68 + c] + __ldg(bias + n0 + gc);
            float lor = 0.f;
            #pragma unroll
            for (int j = 0; j < 16; j++) lor += Tsm[r * 16 + j] * Bl[gc * 17 + j];
            v += 2.0f * lor;
            if (GELU) v = 0.5f * v * (1.0f + erff(v * 0.7071067811865476f));
            C[(size_t)(m0 + r) * N + n0 + gc] = v;
            if (FUSE_T2) { parkF[r * 68 + c] = v; hm = fmaxf(hm, fabsf(v)); }
        }
        if (FUSE_T2) {
            __syncthreads();
            #pragma unroll
            for (int cq = 0; cq < 16; cq++) {
                float4 av = *(float4*)(Apsm + jj * 132 + half * 64 + cq * 4);
                #pragma unroll
                for (int ii = 0; ii < 8; ii++) {
                    float4 hv = *(float4*)(parkF + (rgp * 8 + ii) * 68 + cq * 4);
                    acc2[ii] += hv.x * av.x + hv.y * av.y + hv.z * av.z + hv.w * av.w;
                }
            }
        }
    }
    if (FUSE_T2) {
        #pragma unroll
        for (int ii = 0; ii < 8; ii++)
            Tpart[(size_t)blockIdx.x * ((size_t)M * R)
                  + (size_t)(m0 + rgp * 8 + ii) * R + jj] = acc2[ii];
        #pragma unroll
        for (int o = 16; o; o >>= 1) hm = fmaxf(hm, __shfl_down_sync(0xffffffffu, hm, o));
        if ((tid & 31) == 0) hred[w] = hm;
        __syncthreads();
        if (tid == 0) {
            float m = hred[0];
            #pragma unroll
            for (int i = 1; i < 8; i++) m = fmaxf(m, hred[i]);
            atomicMax(hmax, __float_as_int(m));
        }
    }
}

// ---------------------------------------------------------------------------
extern "C" void kernel_launch(void* const* d_in, const int* in_sizes, int n_in,
                              void* d_out, int out_size) {
    const float* x      = (const float*)d_in[0];
    const float* W_fc   = (const float*)d_in[1];
    const float* b_fc   = (const float*)d_in[2];
    const float* A_fc   = (const float*)d_in[3];
    const float* B_fc   = (const float*)d_in[4];
    const float* W_proj = (const float*)d_in[5];
    const float* b_proj = (const float*)d_in[6];
    const float* A_proj = (const float*)d_in[7];
    const float* B_proj = (const float*)d_in[8];
    float* out = (float*)d_out;

    const int M = in_sizes[0] / N_EMBD;   // 8192
    constexpr int SMEM_GEMM = 61440;

    cudaFuncSetAttribute(gemm_kernel<true, true>,
                         cudaFuncAttributeMaxDynamicSharedMemorySize, SMEM_GEMM);
    cudaFuncSetAttribute(gemm_kernel<false, false>,
                         cudaFuncAttributeMaxDynamicSharedMemorySize, SMEM_GEMM);

    void* p;
    cudaGetSymbolAddress(&p, g_xq);      signed char* xq      = (signed char*)p;
    cudaGetSymbolAddress(&p, g_wq_fc);   signed char* wq_fc   = (signed char*)p;
    cudaGetSymbolAddress(&p, g_wq_proj); signed char* wq_proj = (signed char*)p;
    cudaGetSymbolAddress(&p, g_h);       float* h     = (float*)p;
    cudaGetSymbolAddress(&p, g_hq);      signed char* hq = (signed char*)p;
    cudaGetSymbolAddress(&p, g_t1);      float* t1    = (float*)p;
    cudaGetSymbolAddress(&p, g_t2);      float* t2    = (float*)p;
    cudaGetSymbolAddress(&p, g_tpart);   float* tpart = (float*)p;
    cudaGetSymbolAddress(&p, g_maxbits); int* mb      = (int*)p;

    init_kernel<<<1, 32>>>(mb);

    absmax_kernel<<<512, 256>>>((const float4*)W_fc,   D_FF * N_EMBD / 4, mb + 1);
    absmax_kernel<<<512, 256>>>((const float4*)W_proj, N_EMBD * D_FF / 4, mb + 2);

    // fused max|x| + t1 = x @ A_fc^T
    rowdot_x_kernel<<<M / 64, 256>>>(x, A_fc, N_EMBD, t1, mb + 0);

    quant_kernel<<<2048, 256>>>((const float4*)x,      M * N_EMBD / 4,    mb + 0, (char4*)xq);
    quant_kernel<<<1024, 256>>>((const float4*)W_fc,   D_FF * N_EMBD / 4, mb + 1, (char4*)wq_fc);
    quant_kernel<<<1024, 256>>>((const float4*)W_proj, N_EMBD * D_FF / 4, mb + 2, (char4*)wq_proj);

    // GEMM1 + bias + LoRA + GELU -> h; fused partial t2 + max|h|
    gemm_kernel<true, true><<<dim3(D_FF / 128, M / 128), 256, SMEM_GEMM>>>(
        xq, wq_fc, b_fc, t1, B_fc, mb + 0, mb + 1, h,
        A_proj, tpart, mb + 3, M, D_FF, N_EMBD);

    reduce_t2_kernel<<<(M * R + 255) / 256, 256>>>(tpart, t2, M * R, NB2);

    quant_kernel<<<4096, 256>>>((const float4*)h, M * D_FF / 4, mb + 3, (char4*)hq);

    // GEMM2 + bias + LoRA -> out
    gemm_kernel<false, false><<<dim3(N_EMBD / 128, M / 128), 256, SMEM_GEMM>>>(
        hq, wq_proj, b_proj, t2, B_proj, mb + 3, mb + 2, out,
        nullptr, nullptr, nullptr, M, N_EMBD, D_FF);
}

// round 6
// speedup vs baseline: 3.2681x; 1.2170x over previous
#include <cuda_runtime.h>
#include <cuda_bf16.h>
#include <cstdint>

static constexpr int N_EMBD = 1024;
static constexpr int D_FF   = 4096;
static constexpr int MAX_M  = 8192;
static constexpr int R      = 16;
static constexpr int NB2    = D_FF / 128;   // GEMM1 n-blocks = t2 partial slices (32)

// ---------------- scratch (device globals; no allocations allowed) ----------
__device__ signed char g_xq[(size_t)MAX_M * N_EMBD];
__device__ signed char g_wq_fc[(size_t)D_FF * N_EMBD];
__device__ signed char g_wq_proj[(size_t)N_EMBD * D_FF];
__device__ float       g_h[(size_t)MAX_M * D_FF];
__device__ signed char g_hq[(size_t)MAX_M * D_FF];
__device__ float       g_t1[(size_t)MAX_M * R];
__device__ float       g_t2[(size_t)MAX_M * R];
__device__ float       g_tpart[(size_t)NB2 * MAX_M * R];
__device__ int         g_maxbits[4];        // |x|,|W_fc|,|W_proj|,|h|

__device__ __forceinline__ void cp_async16(void* d, const void* s) {
    unsigned u = (unsigned)__cvta_generic_to_shared(d);
    asm volatile("cp.async.cg.shared.global [%0], [%1], 16;\n" :: "r"(u), "l"(s));
}
__device__ __forceinline__ void cp_commit() {
    asm volatile("cp.async.commit_group;\n" ::: "memory");
}
__device__ __forceinline__ uint32_t smem_u32(const void* p) {
    return (uint32_t)__cvta_generic_to_shared(p);
}
__device__ __forceinline__ void ldsm4(uint32_t* r, uint32_t addr) {
    asm volatile("ldmatrix.sync.aligned.m8n8.x4.shared.b16 {%0,%1,%2,%3}, [%4];"
        : "=r"(r[0]), "=r"(r[1]), "=r"(r[2]), "=r"(r[3]) : "r"(addr));
}
__device__ __forceinline__ void imma(int* d, const uint32_t* a, const uint32_t* b) {
    asm volatile("mma.sync.aligned.m16n8k32.row.col.s32.s8.s8.s32 "
        "{%0,%1,%2,%3}, {%4,%5,%6,%7}, {%8,%9}, {%0,%1,%2,%3};"
        : "+r"(d[0]), "+r"(d[1]), "+r"(d[2]), "+r"(d[3])
        : "r"(a[0]), "r"(a[1]), "r"(a[2]), "r"(a[3]), "r"(b[0]), "r"(b[1]));
}

// ---------------------------------------------------------------------------
__global__ void init_kernel(int* mb) { if (threadIdx.x < 4) mb[threadIdx.x] = 0; }

__global__ void absmax_kernel(const float4* __restrict__ x, int n4, int* __restrict__ out) {
    float m = 0.f;
    for (int i = blockIdx.x * blockDim.x + threadIdx.x; i < n4; i += gridDim.x * blockDim.x) {
        float4 v = x[i];
        m = fmaxf(m, fmaxf(fmaxf(fabsf(v.x), fabsf(v.y)), fmaxf(fabsf(v.z), fabsf(v.w))));
    }
    #pragma unroll
    for (int o = 16; o; o >>= 1) m = fmaxf(m, __shfl_down_sync(0xffffffffu, m, o));
    __shared__ float sm[8];
    if ((threadIdx.x & 31) == 0) sm[threadIdx.x >> 5] = m;
    __syncthreads();
    if (threadIdx.x == 0) {
        float mm = sm[0];
        #pragma unroll
        for (int w = 1; w < 8; w++) mm = fmaxf(mm, sm[w]);
        atomicMax(out, __float_as_int(mm));
    }
}

// t1 = X @ A^T fused abs-max (unchanged; proven @32us)
__global__ void __launch_bounds__(256) rowdot_x_kernel(
    const float* __restrict__ X, const float* __restrict__ A, int K,
    float* __restrict__ T, int* __restrict__ maxout)
{
    constexpr int LDS = 36;
    constexpr int STG = (64 + 16) * LDS;
    __shared__ __align__(16) float sm[3 * STG];
    __shared__ float mred[8];
    const int tid = threadIdx.x;
    const int m0  = blockIdx.x * 64;
    const int rg  = tid >> 3, cg = tid & 7;
    const float* Xg = X + (size_t)m0 * K;

    auto issue = [&](int kt) {
        float* Xs = sm + (kt % 3) * STG;
        float* As = Xs + 64 * LDS;
        #pragma unroll
        for (int l = 0; l < 2; l++) {
            int i = tid + l * 256, r = i >> 3, c = i & 7;
            cp_async16(Xs + r * LDS + c * 4, Xg + (size_t)r * K + kt * 32 + c * 4);
        }
        if (tid < 128) {
            int r = tid >> 3, c = tid & 7;
            cp_async16(As + r * LDS + c * 4, A + (size_t)r * K + kt * 32 + c * 4);
        }
        cp_commit();
    };

    const int KT = K / 32;
    issue(0); issue(1);
    float acc[2][2] = {};
    float mx = 0.f;

    for (int kt = 0; kt < KT; kt++) {
        asm volatile("cp.async.wait_group 1;\n" ::: "memory");
        __syncthreads();
        if (kt + 2 < KT) issue(kt + 2); else cp_commit();
        const float* Xs = sm + (kt % 3) * STG;
        const float* As = Xs + 64 * LDS;
        #pragma unroll
        for (int kq = 0; kq < 8; kq++) {
            float4 xv0 = *(const float4*)(Xs + (rg * 2)     * LDS + kq * 4);
            float4 xv1 = *(const float4*)(Xs + (rg * 2 + 1) * LDS + kq * 4);
            float4 av0 = *(const float4*)(As + (cg * 2)     * LDS + kq * 4);
            float4 av1 = *(const float4*)(As + (cg * 2 + 1) * LDS + kq * 4);
            mx = fmaxf(mx, fmaxf(fmaxf(fabsf(xv0.x), fabsf(xv0.y)), fmaxf(fabsf(xv0.z), fabsf(xv0.w))));
            mx = fmaxf(mx, fmaxf(fmaxf(fabsf(xv1.x), fabsf(xv1.y)), fmaxf(fabsf(xv1.z), fabsf(xv1.w))));
            acc[0][0] += xv0.x*av0.x + xv0.y*av0.y + xv0.z*av0.z + xv0.w*av0.w;
            acc[0][1] += xv0.x*av1.x + xv0.y*av1.y + xv0.z*av1.z + xv0.w*av1.w;
            acc[1][0] += xv1.x*av0.x + xv1.y*av0.y + xv1.z*av0.z + xv1.w*av0.w;
            acc[1][1] += xv1.x*av1.x + xv1.y*av1.y + xv1.z*av1.z + xv1.w*av1.w;
        }
        __syncthreads();
    }
    #pragma unroll
    for (int ii = 0; ii < 2; ii++)
        #pragma unroll
        for (int jj = 0; jj < 2; jj++)
            T[(size_t)(m0 + rg * 2 + ii) * R + cg * 2 + jj] = acc[ii][jj];

    #pragma unroll
    for (int o = 16; o; o >>= 1) mx = fmaxf(mx, __shfl_down_sync(0xffffffffu, mx, o));
    if ((tid & 31) == 0) mred[tid >> 5] = mx;
    __syncthreads();
    if (tid == 0) {
        float m = mred[0];
        #pragma unroll
        for (int i = 1; i < 8; i++) m = fmaxf(m, mred[i]);
        atomicMax(maxout, __float_as_int(m));
    }
}

// q = clip(round(v/scale),-127,127) stored as int8.
__global__ void quant_kernel(const float4* __restrict__ src, int n4,
                             const int* __restrict__ mb, char4* __restrict__ dst) {
    const float s = fmaxf(__int_as_float(*mb), 1e-8f) / 127.0f;
    for (int i = blockIdx.x * blockDim.x + threadIdx.x; i < n4; i += gridDim.x * blockDim.x) {
        float4 v = src[i];
        char4 q;
        q.x = (signed char)(int)fminf(fmaxf(rintf(v.x / s), -127.f), 127.f);
        q.y = (signed char)(int)fminf(fmaxf(rintf(v.y / s), -127.f), 127.f);
        q.z = (signed char)(int)fminf(fmaxf(rintf(v.z / s), -127.f), 127.f);
        q.w = (signed char)(int)fminf(fmaxf(rintf(v.w / s), -127.f), 127.f);
        dst[i] = q;
    }
}

__global__ void reduce_t2_kernel(const float* __restrict__ Tpart, float* __restrict__ T2,
                                 int n, int nb) {
    int i = blockIdx.x * blockDim.x + threadIdx.x;
    if (i < n) {
        float s = 0.f;
        for (int b = 0; b < nb; b++) s += Tpart[(size_t)b * n + i];
        T2[i] = s;
    }
}

// ---------------------------------------------------------------------------
// int8 GEMM: C = s*(Aq@Bq^T) + bias + 2*(T@Blora^T)  [+GELU]
// BM=128 BN=128 BK=64, 3-stage cp.async, raw mma.m16n8k32.s8 + ldmatrix.x4.
// 8 warps: 2(m) x 4(n), warp tile 64x32. One __syncthreads per mainloop iter.
// FUSE_T2: emits per-n-block partials of gelu(h)@Ap^T and max|h|.
// ---------------------------------------------------------------------------
template <bool GELU, bool FUSE_T2>
__global__ void __launch_bounds__(256, 2) gemm_kernel(
    const signed char* __restrict__ Aq, const signed char* __restrict__ Bq,
    const float* __restrict__ bias, const float* __restrict__ T,
    const float* __restrict__ Blora, const int* __restrict__ mbA,
    const int* __restrict__ mbW, float* __restrict__ C,
    const float* __restrict__ Ap, float* __restrict__ Tpart, int* __restrict__ hmax,
    int M, int N, int K)
{
    constexpr int BM = 128, BN = 128, BK = 64, LDA = 80;
    constexpr int STAGE = 2 * BM * LDA;           // A(10240) + B(10240) bytes
    extern __shared__ __align__(16) char smem[];  // 3*20480 = 61440
    __shared__ float hred[8];

    const int tid = threadIdx.x;
    const int lane = tid & 31;
    const int m0 = blockIdx.y * BM, n0 = blockIdx.x * BN;
    const int w = tid >> 5, wm = w & 1, wn = w >> 1;

    const signed char* Agb = Aq + (size_t)m0 * K;
    const signed char* Bgb = Bq + (size_t)n0 * K;

    auto issue = [&](int kt) {
        char* as = smem + (kt % 3) * STAGE;
        char* bs = as + BM * LDA;
        const signed char* ag = Agb + kt * BK;
        const signed char* bg = Bgb + kt * BK;
        #pragma unroll
        for (int l = 0; l < 2; l++) {
            int i = tid + l * 256, r = i >> 2, c = i & 3;
            cp_async16(as + r * LDA + c * 16, ag + (size_t)r * K + c * 16);
        }
        #pragma unroll
        for (int l = 0; l < 2; l++) {
            int i = tid + l * 256, r = i >> 2, c = i & 3;
            cp_async16(bs + r * LDA + c * 16, bg + (size_t)r * K + c * 16);
        }
        cp_commit();
    };

    // ldmatrix per-lane offsets
    // A: lanes 0-15 -> rows 0-15 (k lo 16B); lanes 16-31 -> rows 0-15 (k hi 16B)
    const uint32_t a_off = (uint32_t)((wm * 64 + (lane & 15)) * LDA + ((lane >> 4) << 4));
    // B: lanes 0-7 n0-7 klo; 8-15 n0-7 khi; 16-23 n8-15 klo; 24-31 n8-15 khi
    const int brow = (lane & 7) + ((lane & 16) >> 1);
    const uint32_t b_off = (uint32_t)((wn * 32 + brow) * LDA + (((lane >> 3) & 1) << 4));

    const int KT = K / BK;
    issue(0); issue(1);

    int d[4][4][4];                               // [m16 tile][n8 tile][frag]
    #pragma unroll
    for (int i = 0; i < 4; i++)
        #pragma unroll
        for (int j = 0; j < 4; j++)
            #pragma unroll
            for (int q = 0; q < 4; q++) d[i][j][q] = 0;

    for (int kt = 0; kt < KT; kt++) {
        asm volatile("cp.async.wait_group 1;\n" ::: "memory");
        __syncthreads();
        if (kt + 2 < KT) issue(kt + 2); else cp_commit();

        uint32_t a_s = smem_u32(smem + (kt % 3) * STAGE);
        uint32_t b_s = a_s + BM * LDA;
        #pragma unroll
        for (int ks = 0; ks < 2; ks++) {          // two k32 steps per BK=64
            uint32_t af[4][4], bf[4][2];
            #pragma unroll
            for (int i = 0; i < 4; i++)
                ldsm4(af[i], a_s + a_off + i * (16 * LDA) + ks * 32);
            {
                uint32_t t[4];
                ldsm4(t, b_s + b_off + ks * 32);              // n rows 0-15
                bf[0][0] = t[0]; bf[0][1] = t[1]; bf[1][0] = t[2]; bf[1][1] = t[3];
                ldsm4(t, b_s + b_off + 16 * LDA + ks * 32);   // n rows 16-31
                bf[2][0] = t[0]; bf[2][1] = t[1]; bf[3][0] = t[2]; bf[3][1] = t[3];
            }
            #pragma unroll
            for (int i = 0; i < 4; i++)
                #pragma unroll
                for (int j = 0; j < 4; j++)
                    imma(d[i][j], af[i], bf[j]);
        }
    }
    asm volatile("cp.async.wait_group 0;\n" ::: "memory");
    __syncthreads();

    // ---------------- epilogue (aliases pipeline smem; same as R4) ----------
    const float sA = fmaxf(__int_as_float(*mbA), 1e-8f) / 127.0f;
    const float sW = fmaxf(__int_as_float(*mbW), 1e-8f) / 127.0f;
    const float sc = sA * sW;

    int*   parkI = (int*)smem;                    // [128][68] int/float = 34816 B
    float* parkF = (float*)smem;
    float* Tsm   = (float*)(smem + 34816);        // [128][16]           =  8192 B
    float* Bl    = (float*)(smem + 43008);        // [128][17]           =  8704 B
    float* Apsm  = (float*)(smem + 51712);        // [16][132]           =  8448 B

    for (int i = tid; i < BN * R; i += 256) {
        int r = i >> 4, j = i & 15;
        Bl[r * 17 + j] = Blora[(size_t)(n0 + r) * R + j];
    }
    if (FUSE_T2)
        for (int i = tid; i < R * BN; i += 256) {
            int j = i >> 7, c = i & 127;
            Apsm[j * 132 + c] = Ap[(size_t)j * N + n0 + c];
        }
    #pragma unroll
    for (int l = 0; l < 2; l++)
        ((float4*)Tsm)[tid + l * 256] = ((const float4*)(T + (size_t)m0 * R))[tid + l * 256];

    float hm = 0.f;
    float acc2[8] = {};
    const int jj = tid & 15, rgp = tid >> 4;

    #pragma unroll
    for (int half = 0; half < 2; half++) {
        __syncthreads();
        if ((wn >> 1) == half) {                  // 4 warps park their 128x64 half
            #pragma unroll
            for (int i = 0; i < 4; i++) {
                int r0 = wm * 64 + i * 16 + (lane >> 2);
                #pragma unroll
                for (int j = 0; j < 4; j++) {
                    int c = (wn & 1) * 32 + j * 8 + (lane & 3) * 2;
                    parkI[r0 * 68 + c]           = d[i][j][0];
                    parkI[r0 * 68 + c + 1]       = d[i][j][1];
                    parkI[(r0 + 8) * 68 + c]     = d[i][j][2];
                    parkI[(r0 + 8) * 68 + c + 1] = d[i][j][3];
                }
            }
        }
        __syncthreads();

        for (int idx = tid; idx < BM * 64; idx += 256) {
            int r = idx >> 6, c = idx & 63;
            int gc = half * 64 + c;
            float v = sc * (float)parkI[r * 68 + c] + __ldg(bias + n0 + gc);
            float lor = 0.f;
            #pragma unroll
            for (int j = 0; j < 16; j++) lor += Tsm[r * 16 + j] * Bl[gc * 17 + j];
            v += 2.0f * lor;
            if (GELU) v = 0.5f * v * (1.0f + erff(v * 0.7071067811865476f));
            C[(size_t)(m0 + r) * N + n0 + gc] = v;
            if (FUSE_T2) { parkF[r * 68 + c] = v; hm = fmaxf(hm, fabsf(v)); }
        }
        if (FUSE_T2) {
            __syncthreads();
            #pragma unroll
            for (int cq = 0; cq < 16; cq++) {
                float4 av = *(float4*)(Apsm + jj * 132 + half * 64 + cq * 4);
                #pragma unroll
                for (int ii = 0; ii < 8; ii++) {
                    float4 hv = *(float4*)(parkF + (rgp * 8 + ii) * 68 + cq * 4);
                    acc2[ii] += hv.x * av.x + hv.y * av.y + hv.z * av.z + hv.w * av.w;
                }
            }
        }
    }
    if (FUSE_T2) {
        #pragma unroll
        for (int ii = 0; ii < 8; ii++)
            Tpart[(size_t)blockIdx.x * ((size_t)M * R)
                  + (size_t)(m0 + rgp * 8 + ii) * R + jj] = acc2[ii];
        #pragma unroll
        for (int o = 16; o; o >>= 1) hm = fmaxf(hm, __shfl_down_sync(0xffffffffu, hm, o));
        if ((tid & 31) == 0) hred[w] = hm;
        __syncthreads();
        if (tid == 0) {
            float m = hred[0];
            #pragma unroll
            for (int i = 1; i < 8; i++) m = fmaxf(m, hred[i]);
            atomicMax(hmax, __float_as_int(m));
        }
    }
}

// ---------------------------------------------------------------------------
extern "C" void kernel_launch(void* const* d_in, const int* in_sizes, int n_in,
                              void* d_out, int out_size) {
    const float* x      = (const float*)d_in[0];
    const float* W_fc   = (const float*)d_in[1];
    const float* b_fc   = (const float*)d_in[2];
    const float* A_fc   = (const float*)d_in[3];
    const float* B_fc   = (const float*)d_in[4];
    const float* W_proj = (const float*)d_in[5];
    const float* b_proj = (const float*)d_in[6];
    const float* A_proj = (const float*)d_in[7];
    const float* B_proj = (const float*)d_in[8];
    float* out = (float*)d_out;

    const int M = in_sizes[0] / N_EMBD;   // 8192
    constexpr int SMEM_GEMM = 61440;

    cudaFuncSetAttribute(gemm_kernel<true, true>,
                         cudaFuncAttributeMaxDynamicSharedMemorySize, SMEM_GEMM);
    cudaFuncSetAttribute(gemm_kernel<false, false>,
                         cudaFuncAttributeMaxDynamicSharedMemorySize, SMEM_GEMM);

    void* p;
    cudaGetSymbolAddress(&p, g_xq);      signed char* xq      = (signed char*)p;
    cudaGetSymbolAddress(&p, g_wq_fc);   signed char* wq_fc   = (signed char*)p;
    cudaGetSymbolAddress(&p, g_wq_proj); signed char* wq_proj = (signed char*)p;
    cudaGetSymbolAddress(&p, g_h);       float* h     = (float*)p;
    cudaGetSymbolAddress(&p, g_hq);      signed char* hq = (signed char*)p;
    cudaGetSymbolAddress(&p, g_t1);      float* t1    = (float*)p;
    cudaGetSymbolAddress(&p, g_t2);      float* t2    = (float*)p;
    cudaGetSymbolAddress(&p, g_tpart);   float* tpart = (float*)p;
    cudaGetSymbolAddress(&p, g_maxbits); int* mb      = (int*)p;

    init_kernel<<<1, 32>>>(mb);

    absmax_kernel<<<512, 256>>>((const float4*)W_fc,   D_FF * N_EMBD / 4, mb + 1);
    absmax_kernel<<<512, 256>>>((const float4*)W_proj, N_EMBD * D_FF / 4, mb + 2);

    rowdot_x_kernel<<<M / 64, 256>>>(x, A_fc, N_EMBD, t1, mb + 0);

    quant_kernel<<<2048, 256>>>((const float4*)x,      M * N_EMBD / 4,    mb + 0, (char4*)xq);
    quant_kernel<<<1024, 256>>>((const float4*)W_fc,   D_FF * N_EMBD / 4, mb + 1, (char4*)wq_fc);
    quant_kernel<<<1024, 256>>>((const float4*)W_proj, N_EMBD * D_FF / 4, mb + 2, (char4*)wq_proj);

    // GEMM1 + bias + LoRA + GELU -> h; fused partial t2 + max|h|
    gemm_kernel<true, true><<<dim3(D_FF / 128, M / 128), 256, SMEM_GEMM>>>(
        xq, wq_fc, b_fc, t1, B_fc, mb + 0, mb + 1, h,
        A_proj, tpart, mb + 3, M, D_FF, N_EMBD);

    reduce_t2_kernel<<<(M * R + 255) / 256, 256>>>(tpart, t2, M * R, NB2);

    quant_kernel<<<4096, 256>>>((const float4*)h, M * D_FF / 4, mb + 3, (char4*)hq);

    // GEMM2 + bias + LoRA -> out
    gemm_kernel<false, false><<<dim3(N_EMBD / 128, M / 128), 256, SMEM_GEMM>>>(
        hq, wq_proj, b_proj, t2, B_proj, mb + 3, mb + 2, out,
        nullptr, nullptr, nullptr, M, N_EMBD, D_FF);
}

// round 7
// speedup vs baseline: 3.4665x; 1.0607x over previous
#include <cuda_runtime.h>
#include <cuda_bf16.h>
#include <cstdint>

static constexpr int N_EMBD = 1024;
static constexpr int D_FF   = 4096;
static constexpr int MAX_M  = 8192;
static constexpr int R      = 16;
static constexpr int NB2    = D_FF / 128;   // GEMM1 n-blocks = t2 partial slices (32)

// ---------------- scratch (device globals; no allocations allowed) ----------
__device__ signed char g_xq[(size_t)MAX_M * N_EMBD];
__device__ signed char g_wq_fc[(size_t)D_FF * N_EMBD];
__device__ signed char g_wq_proj[(size_t)N_EMBD * D_FF];
__device__ float       g_h[(size_t)MAX_M * D_FF];
__device__ signed char g_hq[(size_t)MAX_M * D_FF];
__device__ float       g_t1[(size_t)MAX_M * R];
__device__ float       g_t2[(size_t)MAX_M * R];
__device__ float       g_tpart[(size_t)NB2 * MAX_M * R];
__device__ int         g_maxbits[4];        // |x|,|W_fc|,|W_proj|,|h|

__device__ __forceinline__ void cp_async16(void* d, const void* s) {
    unsigned u = (unsigned)__cvta_generic_to_shared(d);
    asm volatile("cp.async.cg.shared.global [%0], [%1], 16;\n" :: "r"(u), "l"(s));
}
__device__ __forceinline__ void cp_commit() {
    asm volatile("cp.async.commit_group;\n" ::: "memory");
}
__device__ __forceinline__ uint32_t smem_u32(const void* p) {
    return (uint32_t)__cvta_generic_to_shared(p);
}
__device__ __forceinline__ void ldsm4(uint32_t* r, uint32_t addr) {
    asm volatile("ldmatrix.sync.aligned.m8n8.x4.shared.b16 {%0,%1,%2,%3}, [%4];"
        : "=r"(r[0]), "=r"(r[1]), "=r"(r[2]), "=r"(r[3]) : "r"(addr));
}
__device__ __forceinline__ void imma(int* d, const uint32_t* a, const uint32_t* b) {
    asm volatile("mma.sync.aligned.m16n8k32.row.col.s32.s8.s8.s32 "
        "{%0,%1,%2,%3}, {%4,%5,%6,%7}, {%8,%9}, {%0,%1,%2,%3};"
        : "+r"(d[0]), "+r"(d[1]), "+r"(d[2]), "+r"(d[3])
        : "r"(a[0]), "r"(a[1]), "r"(a[2]), "r"(a[3]), "r"(b[0]), "r"(b[1]));
}

// ---------------------------------------------------------------------------
__global__ void init_kernel(int* mb) { if (threadIdx.x < 4) mb[threadIdx.x] = 0; }

__global__ void absmax_kernel(const float4* __restrict__ x, int n4, int* __restrict__ out) {
    float m = 0.f;
    for (int i = blockIdx.x * blockDim.x + threadIdx.x; i < n4; i += gridDim.x * blockDim.x) {
        float4 v = x[i];
        m = fmaxf(m, fmaxf(fmaxf(fabsf(v.x), fabsf(v.y)), fmaxf(fabsf(v.z), fabsf(v.w))));
    }
    #pragma unroll
    for (int o = 16; o; o >>= 1) m = fmaxf(m, __shfl_down_sync(0xffffffffu, m, o));
    __shared__ float sm[8];
    if ((threadIdx.x & 31) == 0) sm[threadIdx.x >> 5] = m;
    __syncthreads();
    if (threadIdx.x == 0) {
        float mm = sm[0];
        #pragma unroll
        for (int w = 1; w < 8; w++) mm = fmaxf(mm, sm[w]);
        atomicMax(out, __float_as_int(mm));
    }
}

// ---------------------------------------------------------------------------
// t1 = X @ A^T fused abs-max. BM=16 rows, 128 threads -> grid 512 (occupancy).
// ---------------------------------------------------------------------------
__global__ void __launch_bounds__(128) rowdot_x_kernel(
    const float* __restrict__ X, const float* __restrict__ A, int K,
    float* __restrict__ T, int* __restrict__ maxout)
{
    constexpr int LDS = 36;
    constexpr int STG = 32 * LDS;                 // X(16 rows) + A(16 rows)
    __shared__ __align__(16) float sm[3 * STG];
    __shared__ float mred[4];
    const int tid = threadIdx.x;
    const int m0  = blockIdx.x * 16;
    const int tr  = tid >> 3, tc = tid & 7;       // 16 rows x 8 col-pairs
    const float* Xg = X + (size_t)m0 * K;

    auto issue = [&](int kt) {
        float* Xs = sm + (kt % 3) * STG;
        float* As = Xs + 16 * LDS;
        int r = tid >> 3, c = (tid & 7) * 4;
        cp_async16(Xs + r * LDS + c, Xg + (size_t)r * K + kt * 32 + c);
        cp_async16(As + r * LDS + c, A  + (size_t)r * K + kt * 32 + c);
        cp_commit();
    };

    const int KT = K / 32;
    issue(0); issue(1);
    float acc0 = 0.f, acc1 = 0.f, mx = 0.f;

    for (int kt = 0; kt < KT; kt++) {
        asm volatile("cp.async.wait_group 1;\n" ::: "memory");
        __syncthreads();
        if (kt + 2 < KT) issue(kt + 2); else cp_commit();
        const float* Xs = sm + (kt % 3) * STG;
        const float* As = Xs + 16 * LDS;
        #pragma unroll
        for (int kq = 0; kq < 8; kq++) {
            float4 xv  = *(const float4*)(Xs + tr * LDS + kq * 4);
            float4 av0 = *(const float4*)(As + (tc * 2)     * LDS + kq * 4);
            float4 av1 = *(const float4*)(As + (tc * 2 + 1) * LDS + kq * 4);
            mx = fmaxf(mx, fmaxf(fmaxf(fabsf(xv.x), fabsf(xv.y)), fmaxf(fabsf(xv.z), fabsf(xv.w))));
            acc0 += xv.x*av0.x + xv.y*av0.y + xv.z*av0.z + xv.w*av0.w;
            acc1 += xv.x*av1.x + xv.y*av1.y + xv.z*av1.z + xv.w*av1.w;
        }
        __syncthreads();
    }
    T[(size_t)(m0 + tr) * R + tc * 2]     = acc0;
    T[(size_t)(m0 + tr) * R + tc * 2 + 1] = acc1;

    #pragma unroll
    for (int o = 16; o; o >>= 1) mx = fmaxf(mx, __shfl_down_sync(0xffffffffu, mx, o));
    if ((tid & 31) == 0) mred[tid >> 5] = mx;
    __syncthreads();
    if (tid == 0) {
        float m = fmaxf(fmaxf(mred[0], mred[1]), fmaxf(mred[2], mred[3]));
        atomicMax(maxout, __float_as_int(m));
    }
}

// q = clip(round(v/scale),-127,127) stored as int8.
__global__ void quant_kernel(const float4* __restrict__ src, int n4,
                             const int* __restrict__ mb, char4* __restrict__ dst) {
    const float s = fmaxf(__int_as_float(*mb), 1e-8f) / 127.0f;
    for (int i = blockIdx.x * blockDim.x + threadIdx.x; i < n4; i += gridDim.x * blockDim.x) {
        float4 v = src[i];
        char4 q;
        q.x = (signed char)(int)fminf(fmaxf(rintf(v.x / s), -127.f), 127.f);
        q.y = (signed char)(int)fminf(fmaxf(rintf(v.y / s), -127.f), 127.f);
        q.z = (signed char)(int)fminf(fmaxf(rintf(v.z / s), -127.f), 127.f);
        q.w = (signed char)(int)fminf(fmaxf(rintf(v.w / s), -127.f), 127.f);
        dst[i] = q;
    }
}

__global__ void reduce_t2_kernel(const float* __restrict__ Tpart, float* __restrict__ T2,
                                 int n, int nb) {
    int i = blockIdx.x * blockDim.x + threadIdx.x;
    if (i < n) {
        float s = 0.f;
        for (int b = 0; b < nb; b++) s += Tpart[(size_t)b * n + i];
        T2[i] = s;
    }
}

// ---------------------------------------------------------------------------
// int8 GEMM: C = s*(Aq@Bq^T) + bias + 2*(T@Blora^T)  [+GELU]
// BM=128 BN=128 BK=64, 4-stage cp.async (prefetch distance 3),
// raw mma.m16n8k32.s8 + ldmatrix.x4. 8 warps: 2(m) x 4(n), warp tile 64x32.
// Epilogue: column-per-thread with hoisted bias + LoRA-B registers.
// ---------------------------------------------------------------------------
template <bool GELU, bool FUSE_T2>
__global__ void __launch_bounds__(256, 2) gemm_kernel(
    const signed char* __restrict__ Aq, const signed char* __restrict__ Bq,
    const float* __restrict__ bias, const float* __restrict__ T,
    const float* __restrict__ Blora, const int* __restrict__ mbA,
    const int* __restrict__ mbW, float* __restrict__ C,
    const float* __restrict__ Ap, float* __restrict__ Tpart, int* __restrict__ hmax,
    int M, int N, int K)
{
    constexpr int BM = 128, BN = 128, BK = 64, LDA = 80;
    constexpr int STAGE = 2 * BM * LDA;           // A(10240) + B(10240) bytes
    extern __shared__ __align__(16) char smem[];  // 4*20480 = 81920
    __shared__ float hred[8];

    const int tid = threadIdx.x;
    const int lane = tid & 31;
    const int m0 = blockIdx.y * BM, n0 = blockIdx.x * BN;
    const int w = tid >> 5, wm = w & 1, wn = w >> 1;

    const signed char* Agb = Aq + (size_t)m0 * K;
    const signed char* Bgb = Bq + (size_t)n0 * K;

    auto issue = [&](int kt) {
        char* as = smem + (kt & 3) * STAGE;
        char* bs = as + BM * LDA;
        const signed char* ag = Agb + kt * BK;
        const signed char* bg = Bgb + kt * BK;
        #pragma unroll
        for (int l = 0; l < 2; l++) {
            int i = tid + l * 256, r = i >> 2, c = i & 3;
            cp_async16(as + r * LDA + c * 16, ag + (size_t)r * K + c * 16);
        }
        #pragma unroll
        for (int l = 0; l < 2; l++) {
            int i = tid + l * 256, r = i >> 2, c = i & 3;
            cp_async16(bs + r * LDA + c * 16, bg + (size_t)r * K + c * 16);
        }
        cp_commit();
    };

    const uint32_t a_off = (uint32_t)((wm * 64 + (lane & 15)) * LDA + ((lane >> 4) << 4));
    const int brow = (lane & 7) + ((lane & 16) >> 1);
    const uint32_t b_off = (uint32_t)((wn * 32 + brow) * LDA + (((lane >> 3) & 1) << 4));

    const int KT = K / BK;
    issue(0); issue(1); issue(2);

    int d[4][4][4];
    #pragma unroll
    for (int i = 0; i < 4; i++)
        #pragma unroll
        for (int j = 0; j < 4; j++)
            #pragma unroll
            for (int q = 0; q < 4; q++) d[i][j][q] = 0;

    for (int kt = 0; kt < KT; kt++) {
        asm volatile("cp.async.wait_group 2;\n" ::: "memory");
        __syncthreads();

        uint32_t a_s = smem_u32(smem + (kt & 3) * STAGE);
        uint32_t b_s = a_s + BM * LDA;
        #pragma unroll
        for (int ks = 0; ks < 2; ks++) {
            uint32_t af[4][4], bf[4][2];
            #pragma unroll
            for (int i = 0; i < 4; i++)
                ldsm4(af[i], a_s + a_off + i * (16 * LDA) + ks * 32);
            {
                uint32_t t[4];
                ldsm4(t, b_s + b_off + ks * 32);
                bf[0][0] = t[0]; bf[0][1] = t[1]; bf[1][0] = t[2]; bf[1][1] = t[3];
                ldsm4(t, b_s + b_off + 16 * LDA + ks * 32);
                bf[2][0] = t[0]; bf[2][1] = t[1]; bf[3][0] = t[2]; bf[3][1] = t[3];
            }
            #pragma unroll
            for (int i = 0; i < 4; i++)
                #pragma unroll
                for (int j = 0; j < 4; j++)
                    imma(d[i][j], af[i], bf[j]);
        }
        if (kt + 3 < KT) issue(kt + 3); else cp_commit();
    }
    asm volatile("cp.async.wait_group 0;\n" ::: "memory");
    __syncthreads();

    // ---------------- epilogue (aliases pipeline smem) ----------------
    const float sA = fmaxf(__int_as_float(*mbA), 1e-8f) / 127.0f;
    const float sW = fmaxf(__int_as_float(*mbW), 1e-8f) / 127.0f;
    const float sc = sA * sW;

    int*   parkI = (int*)smem;                    // [128][68]  = 34816 B
    float* parkF = (float*)smem;
    float* Tsm   = (float*)(smem + 34816);        // [128][16]  =  8192 B
    float* Bl    = (float*)(smem + 43008);        // [128][16]  =  8192 B (contig)
    float* Apsm  = (float*)(smem + 51200);        // [16][132]  =  8448 B

    #pragma unroll
    for (int l = 0; l < 2; l++) {                 // Blora [128][16] contiguous
        ((float4*)Bl)[tid + l * 256]  = ((const float4*)(Blora + (size_t)n0 * R))[tid + l * 256];
        ((float4*)Tsm)[tid + l * 256] = ((const float4*)(T + (size_t)m0 * R))[tid + l * 256];
    }
    if (FUSE_T2)
        for (int i = tid; i < R * BN; i += 256) {
            int j = i >> 7, c = i & 127;
            Apsm[j * 132 + c] = Ap[(size_t)j * N + n0 + c];
        }

    float hm = 0.f;
    float acc2[8] = {};
    const int jj = tid & 15, rgp = tid >> 4;
    const int ec = tid & 63, er0 = tid >> 6;      // column-per-thread epilogue map

    #pragma unroll
    for (int half = 0; half < 2; half++) {
        __syncthreads();
        if ((wn >> 1) == half) {                  // 4 warps park their 128x64 half
            #pragma unroll
            for (int i = 0; i < 4; i++) {
                int r0 = wm * 64 + i * 16 + (lane >> 2);
                #pragma unroll
                for (int j = 0; j < 4; j++) {
                    int c = (wn & 1) * 32 + j * 8 + (lane & 3) * 2;
                    parkI[r0 * 68 + c]           = d[i][j][0];
                    parkI[r0 * 68 + c + 1]       = d[i][j][1];
                    parkI[(r0 + 8) * 68 + c]     = d[i][j][2];
                    parkI[(r0 + 8) * 68 + c + 1] = d[i][j][3];
                }
            }
        }
        __syncthreads();

        const int gc = half * 64 + ec;
        const float bsv = __ldg(bias + n0 + gc);
        float4 bl0 = *(float4*)(Bl + gc * 16);
        float4 bl1 = *(float4*)(Bl + gc * 16 + 4);
        float4 bl2 = *(float4*)(Bl + gc * 16 + 8);
        float4 bl3 = *(float4*)(Bl + gc * 16 + 12);

        for (int r = er0; r < BM; r += 4) {
            float4 t0 = *(float4*)(Tsm + r * 16);
            float4 t1 = *(float4*)(Tsm + r * 16 + 4);
            float4 t2v = *(float4*)(Tsm + r * 16 + 8);
            float4 t3 = *(float4*)(Tsm + r * 16 + 12);
            float lor = t0.x*bl0.x + t0.y*bl0.y + t0.z*bl0.z + t0.w*bl0.w
                      + t1.x*bl1.x + t1.y*bl1.y + t1.z*bl1.z + t1.w*bl1.w
                      + t2v.x*bl2.x + t2v.y*bl2.y + t2v.z*bl2.z + t2v.w*bl2.w
                      + t3.x*bl3.x + t3.y*bl3.y + t3.z*bl3.z + t3.w*bl3.w;
            float v = sc * (float)parkI[r * 68 + ec] + bsv + 2.0f * lor;
            if (GELU) v = 0.5f * v * (1.0f + erff(v * 0.7071067811865476f));
            C[(size_t)(m0 + r) * N + n0 + gc] = v;
            if (FUSE_T2) { parkF[r * 68 + ec] = v; hm = fmaxf(hm, fabsf(v)); }
        }
        if (FUSE_T2) {
            __syncthreads();
            #pragma unroll
            for (int cq = 0; cq < 16; cq++) {
                float4 av = *(float4*)(Apsm + jj * 132 + half * 64 + cq * 4);
                #pragma unroll
                for (int ii = 0; ii < 8; ii++) {
                    float4 hv = *(float4*)(parkF + (rgp * 8 + ii) * 68 + cq * 4);
                    acc2[ii] += hv.x * av.x + hv.y * av.y + hv.z * av.z + hv.w * av.w;
                }
            }
        }
    }
    if (FUSE_T2) {
        #pragma unroll
        for (int ii = 0; ii < 8; ii++)
            Tpart[(size_t)blockIdx.x * ((size_t)M * R)
                  + (size_t)(m0 + rgp * 8 + ii) * R + jj] = acc2[ii];
        #pragma unroll
        for (int o = 16; o; o >>= 1) hm = fmaxf(hm, __shfl_down_sync(0xffffffffu, hm, o));
        if ((tid & 31) == 0) hred[w] = hm;
        __syncthreads();
        if (tid == 0) {
            float m = hred[0];
            #pragma unroll
            for (int i = 1; i < 8; i++) m = fmaxf(m, hred[i]);
            atomicMax(hmax, __float_as_int(m));
        }
    }
}

// ---------------------------------------------------------------------------
extern "C" void kernel_launch(void* const* d_in, const int* in_sizes, int n_in,
                              void* d_out, int out_size) {
    const float* x      = (const float*)d_in[0];
    const float* W_fc   = (const float*)d_in[1];
    const float* b_fc   = (const float*)d_in[2];
    const float* A_fc   = (const float*)d_in[3];
    const float* B_fc   = (const float*)d_in[4];
    const float* W_proj = (const float*)d_in[5];
    const float* b_proj = (const float*)d_in[6];
    const float* A_proj = (const float*)d_in[7];
    const float* B_proj = (const float*)d_in[8];
    float* out = (float*)d_out;

    const int M = in_sizes[0] / N_EMBD;   // 8192
    constexpr int SMEM_GEMM = 81920;

    cudaFuncSetAttribute(gemm_kernel<true, true>,
                         cudaFuncAttributeMaxDynamicSharedMemorySize, SMEM_GEMM);
    cudaFuncSetAttribute(gemm_kernel<false, false>,
                         cudaFuncAttributeMaxDynamicSharedMemorySize, SMEM_GEMM);

    void* p;
    cudaGetSymbolAddress(&p, g_xq);      signed char* xq      = (signed char*)p;
    cudaGetSymbolAddress(&p, g_wq_fc);   signed char* wq_fc   = (signed char*)p;
    cudaGetSymbolAddress(&p, g_wq_proj); signed char* wq_proj = (signed char*)p;
    cudaGetSymbolAddress(&p, g_h);       float* h     = (float*)p;
    cudaGetSymbolAddress(&p, g_hq);      signed char* hq = (signed char*)p;
    cudaGetSymbolAddress(&p, g_t1);      float* t1    = (float*)p;
    cudaGetSymbolAddress(&p, g_t2);      float* t2    = (float*)p;
    cudaGetSymbolAddress(&p, g_tpart);   float* tpart = (float*)p;
    cudaGetSymbolAddress(&p, g_maxbits); int* mb      = (int*)p;

    init_kernel<<<1, 32>>>(mb);

    absmax_kernel<<<512, 256>>>((const float4*)W_fc,   D_FF * N_EMBD / 4, mb + 1);
    absmax_kernel<<<512, 256>>>((const float4*)W_proj, N_EMBD * D_FF / 4, mb + 2);

    rowdot_x_kernel<<<M / 16, 128>>>(x, A_fc, N_EMBD, t1, mb + 0);

    quant_kernel<<<2048, 256>>>((const float4*)x,      M * N_EMBD / 4,    mb + 0, (char4*)xq);
    quant_kernel<<<1024, 256>>>((const float4*)W_fc,   D_FF * N_EMBD / 4, mb + 1, (char4*)wq_fc);
    quant_kernel<<<1024, 256>>>((const float4*)W_proj, N_EMBD * D_FF / 4, mb + 2, (char4*)wq_proj);

    // GEMM1 + bias + LoRA + GELU -> h; fused partial t2 + max|h|
    gemm_kernel<true, true><<<dim3(D_FF / 128, M / 128), 256, SMEM_GEMM>>>(
        xq, wq_fc, b_fc, t1, B_fc, mb + 0, mb + 1, h,
        A_proj, tpart, mb + 3, M, D_FF, N_EMBD);

    reduce_t2_kernel<<<(M * R + 255) / 256, 256>>>(tpart, t2, M * R, NB2);

    quant_kernel<<<4096, 256>>>((const float4*)h, M * D_FF / 4, mb + 3, (char4*)hq);

    // GEMM2 + bias + LoRA -> out
    gemm_kernel<false, false><<<dim3(N_EMBD / 128, M / 128), 256, SMEM_GEMM>>>(
        hq, wq_proj, b_proj, t2, B_proj, mb + 3, mb + 2, out,
        nullptr, nullptr, nullptr, M, N_EMBD, D_FF);
}